// round 15
// baseline (speedup 1.0000x reference)
#include <cuda_runtime.h>
#include <cuda_fp16.h>
#include <cstdint>

#define B_   16
#define C_   512
#define HW_  2304              // 48*48
#define EPSF 1e-6f

#define PBSZ   4718592         // per-batch tile bytes (A 2.25MB + B 2.25MB)
#define A_SEC  2359296         // A section size within a batch (18*32*4096)

// ---- scratch: 72 + 2.65 MB = 74.8 MB (< proven-passing 78.3 MB BSS) ----
__device__ char  g_tiles[(size_t)B_ * PBSZ];         // fp16 tiles, all 16 batches
__device__ float g_part[(size_t)B_ * 18 * HW_];      // per-(b,lt) partial ssq per k
__device__ float g_inv[(size_t)B_ * HW_];            // rsqrt per (b,k)

// ---------------- PTX helpers (compute_100-baseline only) ------------------
__device__ __forceinline__ uint32_t smem_u32(const void* p) {
    uint32_t a;
    asm("{ .reg .u64 t; cvta.to.shared.u64 t, %1; cvt.u32.u64 %0, t; }" : "=r"(a) : "l"(p));
    return a;
}
__device__ __forceinline__ void cp16(uint32_t s, const void* g) {
    asm volatile("cp.async.cg.shared.global [%0], [%1], 16;" :: "r"(s), "l"(g) : "memory");
}
__device__ __forceinline__ void cp_commit() {
    asm volatile("cp.async.commit_group;" ::: "memory");
}
template <int N> __device__ __forceinline__ void cp_wait() {
    asm volatile("cp.async.wait_group %0;" :: "n"(N) : "memory");
}
__device__ __forceinline__ void ldsm4t(uint32_t* r, uint32_t a) {
    asm volatile("ldmatrix.sync.aligned.m8n8.x4.trans.shared.b16 {%0,%1,%2,%3}, [%4];"
                 : "=r"(r[0]), "=r"(r[1]), "=r"(r[2]), "=r"(r[3]) : "r"(a));
}
__device__ __forceinline__ void mma16816(float* d, const uint32_t* a, const uint32_t* b) {
    asm volatile(
        "mma.sync.aligned.m16n8k16.row.col.f32.f16.f16.f32 "
        "{%0,%1,%2,%3}, {%4,%5,%6,%7}, {%8,%9}, {%0,%1,%2,%3};"
        : "+f"(d[0]), "+f"(d[1]), "+f"(d[2]), "+f"(d[3])
        : "r"(a[0]), "r"(a[1]), "r"(a[2]), "r"(a[3]), "r"(b[0]), "r"(b[1]));
}
// pack two fp32 -> f16x2 (e0 in low half)
__device__ __forceinline__ uint32_t packh(float e0, float e1) {
    uint32_t u;
    asm("cvt.rn.f16x2.f32 %0, %1, %2;" : "=r"(u) : "f"(e1), "f"(e0));
    return u;
}
// fp16 tile: 16 rows(c) x 128 cols, 256B/row; 16B chunk XOR-swizzled (proven)
#define BSWZ(row, colchunk) ((row) * 256 + ((((colchunk)) ^ ((row) & 7)) << 4))

// ---------------------------------------------------------------------------
// 1) Prep: build ldsm-ready fp16 tile images for one operand.
//    Tile (b, lt, ch) = [c 16 rows][l 128 cols] = 4KB, swizzled.
//    For A (PERM): l = (i%48)*48 + i/48 (w-major flatten); for B: l = i.
// ---------------------------------------------------------------------------
template <bool PERM>
__global__ __launch_bounds__(256) void prep_kernel(const float* __restrict__ src,
                                                   int sec) {
    __shared__ float sm[4][2352];           // 2304 + pad(l/48): conflict-free
    const int tid = threadIdx.x;
    const int c0 = blockIdx.x * 4, b = blockIdx.y;
    char* base = g_tiles + (size_t)b * PBSZ + sec;

#pragma unroll
    for (int cc = 0; cc < 4; cc++) {
        const float* s = src + (size_t)(b * C_ + c0 + cc) * HW_;
        for (int i = tid; i < HW_; i += 256) {
            int l = PERM ? ((i % 48) * 48 + i / 48) : i;
            sm[cc][l + l / 48] = s[i];
        }
    }
    __syncthreads();

    for (int idx = tid; idx < 1152; idx += 256) {   // 18 lt * 4 cc * 16 chunks
        int lt = idx / 64, r = idx & 63;
        int cc = r >> 4, chk = r & 15;
        int c = c0 + cc, row = c & 15, ch = c >> 4;
        char* tb = base + (size_t)(lt * 32 + ch) * 4096;
        int l0 = lt * 128 + chk * 8;
        float f[8];
#pragma unroll
        for (int e = 0; e < 8; e++) { int l = l0 + e; f[e] = sm[cc][l + l / 48]; }
        uint32_t h[4];
#pragma unroll
        for (int q = 0; q < 4; q++) h[q] = packh(f[2 * q], f[2 * q + 1]);
        *(uint4*)(tb + BSWZ(row, chk)) = make_uint4(h[0], h[1], h[2], h[3]);
    }
}

// ---------------------------------------------------------------------------
// 2) Pure fp16 mma.sync GEMM. CTA 128x128, BK=32 chunks (2 x k16 subtiles),
//    3 stages x 16KB = 48KB. 256 threads, 8 warps (2x4), warp tile 64x32.
//    32 MMAs per warp per chunk; one sync/wait per 32 MMAs.
// ---------------------------------------------------------------------------
#define NCH 16             // chunks of K=32
#define STG 16384          // stage: A 8K (2 x 4K) | B 8K (2 x 4K)
#define SMEM_TOT (3 * STG) // 48KB

__global__ __launch_bounds__(256, 2) void corr_gemm(float* __restrict__ out) {
    extern __shared__ char smem[];
    const uint32_t sb = smem_u32(smem);
    const int tid = threadIdx.x;
    const int wid = tid >> 5, ln = tid & 31;
    const int wm = wid >> 2, wn = wid & 3;       // 2 x 4 warps

    const int kt = blockIdx.x, lt = blockIdx.y, b = blockIdx.z;
    const int k0 = kt * 128, l0 = lt * 128;

    const char* tA = g_tiles + (size_t)b * PBSZ + (size_t)(lt * 32) * 4096;
    const char* tB = g_tiles + (size_t)b * PBSZ + A_SEC + (size_t)(kt * 32) * 4096;

    float acc[4][4][4];
#pragma unroll
    for (int i = 0; i < 4; i++)
#pragma unroll
        for (int j = 0; j < 4; j++)
#pragma unroll
            for (int q = 0; q < 4; q++) acc[i][j][q] = 0.f;

#define LOAD_STAGE(CH, SLOT) do {                                              \
        uint32_t st_ = sb + (SLOT) * STG + tid * 16;                           \
        const char* a_ = tA + (size_t)(CH) * 8192 + tid * 16;                  \
        const char* b_ = tB + (size_t)(CH) * 8192 + tid * 16;                  \
        cp16(st_,         a_);                                                 \
        cp16(st_ + 4096,  a_ + 4096);                                          \
        cp16(st_ + 8192,  b_);                                                 \
        cp16(st_ + 12288, b_ + 4096);                                          \
    } while (0)

    LOAD_STAGE(0, 0); cp_commit();
    LOAD_STAGE(1, 1); cp_commit();

    // ldmatrix.trans addresses (proven formulas)
    const int g8 = ln >> 3, l7 = ln & 7;
    const int akrow = (g8 >> 1) * 8 + l7;
    uint32_t aoff[4], boff[2];
#pragma unroll
    for (int mt = 0; mt < 4; mt++)
        aoff[mt] = BSWZ(akrow, (wm * 64 + mt * 16 + (g8 & 1) * 8) >> 3);
    const int bkrow = (g8 & 1) * 8 + l7;
#pragma unroll
    for (int p = 0; p < 2; p++)
        boff[p] = BSWZ(bkrow, (wn * 32 + p * 16 + (g8 >> 1) * 8) >> 3);

    int slot = 0, pslot = 2;
    for (int ch = 0; ch < NCH; ch++) {
        cp_wait<1>();
        __syncthreads();
        if (ch + 2 < NCH) LOAD_STAGE(ch + 2, pslot);
        cp_commit();

        const uint32_t stage = sb + slot * STG;
#pragma unroll
        for (int ks = 0; ks < 2; ks++) {
            const uint32_t st = stage + ks * 4096;
            uint32_t bb0[4], bb1[4];
            ldsm4t(bb0, st + 8192 + boff[0]);
            ldsm4t(bb1, st + 8192 + boff[1]);
#pragma unroll
            for (int mt = 0; mt < 4; mt++) {
                uint32_t aa[4];
                ldsm4t(aa, st + aoff[mt]);
                mma16816(acc[mt][0], aa, bb0);
                mma16816(acc[mt][1], aa, bb0 + 2);
                mma16816(acc[mt][2], aa, bb1);
                mma16816(acc[mt][3], aa, bb1 + 2);
            }
        }
        slot = (slot == 2) ? 0 : slot + 1;
        pslot = (pslot == 2) ? 0 : pslot + 1;
    }
    cp_wait<0>();

    // Epilogue: ReLU + store + per-thread ssq over its 8 columns
    float ssq[8];
#pragma unroll
    for (int q = 0; q < 8; q++) ssq[q] = 0.f;

    const size_t obase = (size_t)b * HW_ * HW_;
#pragma unroll
    for (int mt = 0; mt < 4; mt++) {
        int l_lo = l0 + wm * 64 + mt * 16 + (ln >> 2);
#pragma unroll
        for (int nt = 0; nt < 4; nt++) {
            int kcol = k0 + wn * 32 + nt * 8 + (ln & 3) * 2;
            float2 v0, v1;
            v0.x = fmaxf(acc[mt][nt][0], 0.f);
            v0.y = fmaxf(acc[mt][nt][1], 0.f);
            v1.x = fmaxf(acc[mt][nt][2], 0.f);
            v1.y = fmaxf(acc[mt][nt][3], 0.f);
            ssq[nt * 2]     += v0.x * v0.x + v1.x * v1.x;
            ssq[nt * 2 + 1] += v0.y * v0.y + v1.y * v1.y;
            *(float2*)(out + obase + (size_t)l_lo * HW_ + kcol)       = v0;
            *(float2*)(out + obase + (size_t)(l_lo + 8) * HW_ + kcol) = v1;
        }
    }

    // Deterministic CTA reduction: red[col 0..127][slot 0..15]
    __syncthreads();
    float* red = (float*)smem;
    const int rslot = wm * 8 + (ln >> 2);
#pragma unroll
    for (int nt = 0; nt < 4; nt++)
#pragma unroll
        for (int e = 0; e < 2; e++) {
            int col = wn * 32 + nt * 8 + (ln & 3) * 2 + e;
            red[col * 17 + rslot] = ssq[nt * 2 + e];
        }
    __syncthreads();
    if (tid < 128) {
        float s = 0.f;
#pragma unroll
        for (int r = 0; r < 16; r++) s += red[tid * 17 + r];
        g_part[((size_t)b * 18 + lt) * HW_ + k0 + tid] = s;
    }
}

// ---------------------------------------------------------------------------
// 3) Reduce 18 partials per (b,k) -> rsqrt. Deterministic.
// ---------------------------------------------------------------------------
__global__ __launch_bounds__(256) void reduce2_kernel() {
    int i = blockIdx.x * 256 + threadIdx.x;          // < 16*2304
    int b = i / HW_, k = i - b * HW_;
    float s = 0.f;
#pragma unroll
    for (int lt = 0; lt < 18; lt++)
        s += g_part[((size_t)b * 18 + lt) * HW_ + k];
    g_inv[i] = rsqrtf(s + EPSF);
}

// ---------------------------------------------------------------------------
// 4) Scale rows by per-(b,k) inverse norm. float4 vectorized.
// ---------------------------------------------------------------------------
__global__ __launch_bounds__(256) void normalize_kernel(float* __restrict__ out) {
    const size_t per_b = (size_t)HW_ * HW_ / 4;
    size_t i4 = (size_t)blockIdx.x * blockDim.x + threadIdx.x;
    int b = (int)(i4 / per_b);
    size_t rem = i4 - (size_t)b * per_b;
    int k4 = (int)(rem % (HW_ / 4));
    float4 inv = ((const float4*)g_inv)[b * (HW_ / 4) + k4];
    float4* p = (float4*)out + i4;
    float4 v = *p;
    v.x *= inv.x; v.y *= inv.y; v.z *= inv.z; v.w *= inv.w;
    *p = v;
}

// ---------------------------------------------------------------------------
extern "C" void kernel_launch(void* const* d_in, const int* in_sizes, int n_in,
                              void* d_out, int out_size) {
    const float* A  = (const float*)d_in[0];
    const float* Bf = (const float*)d_in[1];
    float* out = (float*)d_out;

    cudaFuncSetAttribute(corr_gemm, cudaFuncAttributeMaxDynamicSharedMemorySize, SMEM_TOT);

    dim3 pg(C_ / 4, B_);
    prep_kernel<true ><<<pg, 256>>>(A,  0);       // A tiles
    prep_kernel<false><<<pg, 256>>>(Bf, A_SEC);   // B tiles

    dim3 gg(18, 18, B_);
    corr_gemm<<<gg, 256, SMEM_TOT>>>(out);

    reduce2_kernel<<<(B_ * HW_) / 256, 256>>>();

    unsigned n4blocks = (unsigned)(((size_t)B_ * HW_ * HW_ / 4) / 256);
    normalize_kernel<<<n4blocks, 256>>>(out);
}

// round 16
// speedup vs baseline: 1.0195x; 1.0195x over previous
#include <cuda_runtime.h>
#include <cuda_fp16.h>
#include <cstdint>

#define B_   16
#define C_   512
#define HW_  2304              // 48*48
#define EPSF 1e-6f

#define PBSZ   4718592         // per-batch tile bytes (A 2.25MB + B 2.25MB)
#define A_SEC  2359296         // A section size within a batch (18*32*4096)

// ---- scratch: 72 + 2.65 MB = 74.8 MB (< proven-passing 78.3 MB BSS) ----
__device__ char  g_tiles[(size_t)B_ * PBSZ];         // fp16 tiles, all 16 batches
__device__ float g_part[(size_t)B_ * 18 * HW_];      // per-(b,lt) partial ssq per k
__device__ float g_inv[(size_t)B_ * HW_];            // rsqrt per (b,k)

// ---------------- PTX helpers (compute_100-baseline only) ------------------
__device__ __forceinline__ uint32_t smem_u32(const void* p) {
    uint32_t a;
    asm("{ .reg .u64 t; cvta.to.shared.u64 t, %1; cvt.u32.u64 %0, t; }" : "=r"(a) : "l"(p));
    return a;
}
__device__ __forceinline__ void cp16(uint32_t s, const void* g) {
    asm volatile("cp.async.cg.shared.global [%0], [%1], 16;" :: "r"(s), "l"(g) : "memory");
}
__device__ __forceinline__ void cp_commit() {
    asm volatile("cp.async.commit_group;" ::: "memory");
}
template <int N> __device__ __forceinline__ void cp_wait() {
    asm volatile("cp.async.wait_group %0;" :: "n"(N) : "memory");
}
__device__ __forceinline__ void ldsm4t(uint32_t* r, uint32_t a) {
    asm volatile("ldmatrix.sync.aligned.m8n8.x4.trans.shared.b16 {%0,%1,%2,%3}, [%4];"
                 : "=r"(r[0]), "=r"(r[1]), "=r"(r[2]), "=r"(r[3]) : "r"(a));
}
__device__ __forceinline__ void mma16816(float* d, const uint32_t* a, const uint32_t* b) {
    asm volatile(
        "mma.sync.aligned.m16n8k16.row.col.f32.f16.f16.f32 "
        "{%0,%1,%2,%3}, {%4,%5,%6,%7}, {%8,%9}, {%0,%1,%2,%3};"
        : "+f"(d[0]), "+f"(d[1]), "+f"(d[2]), "+f"(d[3])
        : "r"(a[0]), "r"(a[1]), "r"(a[2]), "r"(a[3]), "r"(b[0]), "r"(b[1]));
}
// pack two fp32 -> f16x2 (e0 in low half)
__device__ __forceinline__ uint32_t packh(float e0, float e1) {
    uint32_t u;
    asm("cvt.rn.f16x2.f32 %0, %1, %2;" : "=r"(u) : "f"(e1), "f"(e0));
    return u;
}
// fp16 tile: 16 rows(c) x 128 cols, 256B/row; 16B chunk XOR-swizzled (proven)
#define BSWZ(row, colchunk) ((row) * 256 + ((((colchunk)) ^ ((row) & 7)) << 4))

// ---------------------------------------------------------------------------
// 1) Prep (merged A+B): build ldsm-ready fp16 tile images.
//    blockIdx.z = 0 -> A (permuted l), 1 -> B (identity l).
// ---------------------------------------------------------------------------
__global__ __launch_bounds__(256) void prep_kernel(const float* __restrict__ Asrc,
                                                   const float* __restrict__ Bsrc) {
    __shared__ float sm[4][2352];           // 2304 + pad(l/48): conflict-free
    const int tid = threadIdx.x;
    const int c0 = blockIdx.x * 4, b = blockIdx.y;
    const int isB = blockIdx.z;
    const float* src = isB ? Bsrc : Asrc;
    char* base = g_tiles + (size_t)b * PBSZ + (isB ? A_SEC : 0);

#pragma unroll
    for (int cc = 0; cc < 4; cc++) {
        const float* s = src + (size_t)(b * C_ + c0 + cc) * HW_;
        for (int i = tid; i < HW_; i += 256) {
            int l = isB ? i : ((i % 48) * 48 + i / 48);
            sm[cc][l + l / 48] = s[i];
        }
    }
    __syncthreads();

    for (int idx = tid; idx < 1152; idx += 256) {   // 18 lt * 4 cc * 16 chunks
        int lt = idx / 64, r = idx & 63;
        int cc = r >> 4, chk = r & 15;
        int c = c0 + cc, row = c & 15, ch = c >> 4;
        char* tb = base + (size_t)(lt * 32 + ch) * 4096;
        int l0 = lt * 128 + chk * 8;
        float f[8];
#pragma unroll
        for (int e = 0; e < 8; e++) { int l = l0 + e; f[e] = sm[cc][l + l / 48]; }
        uint32_t h[4];
#pragma unroll
        for (int q = 0; q < 4; q++) h[q] = packh(f[2 * q], f[2 * q + 1]);
        *(uint4*)(tb + BSWZ(row, chk)) = make_uint4(h[0], h[1], h[2], h[3]);
    }
}

// ---------------------------------------------------------------------------
// 2) Pure fp16 mma.sync GEMM. CTA 128x128, BK=16 chunks of 8KB (R12-proven),
//    SIX stages = 48KB, TWO chunks consumed per wait+sync (16 syncs total).
//    256 threads, 8 warps (2x4), warp tile 64x32, 16 MMAs/warp/chunk.
// ---------------------------------------------------------------------------
#define NCH 32             // chunks of K=16
#define STG 8192           // stage: A 4K | B 4K
#define NSTG 6
#define SMEM_TOT (NSTG * STG)   // 48KB

__global__ __launch_bounds__(256, 2) void corr_gemm(float* __restrict__ out) {
    extern __shared__ char smem[];
    const uint32_t sb = smem_u32(smem);
    const int tid = threadIdx.x;
    const int wid = tid >> 5, ln = tid & 31;
    const int wm = wid >> 2, wn = wid & 3;       // 2 x 4 warps

    const int kt = blockIdx.x, lt = blockIdx.y, b = blockIdx.z;
    const int k0 = kt * 128, l0 = lt * 128;

    const char* tA = g_tiles + (size_t)b * PBSZ + (size_t)(lt * 32) * 4096;
    const char* tB = g_tiles + (size_t)b * PBSZ + A_SEC + (size_t)(kt * 32) * 4096;

    float acc[4][4][4];
#pragma unroll
    for (int i = 0; i < 4; i++)
#pragma unroll
        for (int j = 0; j < 4; j++)
#pragma unroll
            for (int q = 0; q < 4; q++) acc[i][j][q] = 0.f;

#define LOAD_STAGE(CH, SLOT) do {                                              \
        uint32_t st_ = sb + (SLOT) * STG + tid * 16;                           \
        cp16(st_,        tA + (size_t)(CH) * 4096 + tid * 16);                 \
        cp16(st_ + 4096, tB + (size_t)(CH) * 4096 + tid * 16);                 \
    } while (0)

    LOAD_STAGE(0, 0); cp_commit();
    LOAD_STAGE(1, 1); cp_commit();
    LOAD_STAGE(2, 2); cp_commit();
    LOAD_STAGE(3, 3); cp_commit();

    // ldmatrix.trans addresses (proven formulas)
    const int g8 = ln >> 3, l7 = ln & 7;
    const int akrow = (g8 >> 1) * 8 + l7;
    uint32_t aoff[4], boff[2];
#pragma unroll
    for (int mt = 0; mt < 4; mt++)
        aoff[mt] = BSWZ(akrow, (wm * 64 + mt * 16 + (g8 & 1) * 8) >> 3);
    const int bkrow = (g8 & 1) * 8 + l7;
#pragma unroll
    for (int p = 0; p < 2; p++)
        boff[p] = BSWZ(bkrow, (wn * 32 + p * 16 + (g8 >> 1) * 8) >> 3);

    int s0 = 0;                                  // slot of even chunk ch
    for (int ch = 0; ch < NCH; ch += 2) {
        if (ch < NCH - 2) cp_wait<2>(); else cp_wait<0>();
        __syncthreads();
        // issue next two chunks; their slots were consumed a full iter ago
        int sn = s0 + 4; if (sn >= NSTG) sn -= NSTG;
        if (ch + 4 < NCH) { LOAD_STAGE(ch + 4, sn);     cp_commit(); }
        if (ch + 5 < NCH) { LOAD_STAGE(ch + 5, sn + 1); cp_commit(); }

#pragma unroll
        for (int sub = 0; sub < 2; sub++) {
            const uint32_t st = sb + (s0 + sub) * STG;
            uint32_t bb0[4], bb1[4];
            ldsm4t(bb0, st + 4096 + boff[0]);
            ldsm4t(bb1, st + 4096 + boff[1]);
#pragma unroll
            for (int mt = 0; mt < 4; mt++) {
                uint32_t aa[4];
                ldsm4t(aa, st + aoff[mt]);
                mma16816(acc[mt][0], aa, bb0);
                mma16816(acc[mt][1], aa, bb0 + 2);
                mma16816(acc[mt][2], aa, bb1);
                mma16816(acc[mt][3], aa, bb1 + 2);
            }
        }
        s0 += 2; if (s0 >= NSTG) s0 -= NSTG;
    }

    // Epilogue: ReLU + store + per-thread ssq over its 8 columns
    float ssq[8];
#pragma unroll
    for (int q = 0; q < 8; q++) ssq[q] = 0.f;

    const size_t obase = (size_t)b * HW_ * HW_;
#pragma unroll
    for (int mt = 0; mt < 4; mt++) {
        int l_lo = l0 + wm * 64 + mt * 16 + (ln >> 2);
#pragma unroll
        for (int nt = 0; nt < 4; nt++) {
            int kcol = k0 + wn * 32 + nt * 8 + (ln & 3) * 2;
            float2 v0, v1;
            v0.x = fmaxf(acc[mt][nt][0], 0.f);
            v0.y = fmaxf(acc[mt][nt][1], 0.f);
            v1.x = fmaxf(acc[mt][nt][2], 0.f);
            v1.y = fmaxf(acc[mt][nt][3], 0.f);
            ssq[nt * 2]     += v0.x * v0.x + v1.x * v1.x;
            ssq[nt * 2 + 1] += v0.y * v0.y + v1.y * v1.y;
            *(float2*)(out + obase + (size_t)l_lo * HW_ + kcol)       = v0;
            *(float2*)(out + obase + (size_t)(l_lo + 8) * HW_ + kcol) = v1;
        }
    }

    // Deterministic CTA reduction: red[col 0..127][slot 0..15]
    __syncthreads();
    float* red = (float*)smem;
    const int rslot = wm * 8 + (ln >> 2);
#pragma unroll
    for (int nt = 0; nt < 4; nt++)
#pragma unroll
        for (int e = 0; e < 2; e++) {
            int col = wn * 32 + nt * 8 + (ln & 3) * 2 + e;
            red[col * 17 + rslot] = ssq[nt * 2 + e];
        }
    __syncthreads();
    if (tid < 128) {
        float s = 0.f;
#pragma unroll
        for (int r = 0; r < 16; r++) s += red[tid * 17 + r];
        g_part[((size_t)b * 18 + lt) * HW_ + k0 + tid] = s;
    }
}

// ---------------------------------------------------------------------------
// 3) Reduce 18 partials per (b,k) -> rsqrt. Deterministic.
// ---------------------------------------------------------------------------
__global__ __launch_bounds__(256) void reduce2_kernel() {
    int i = blockIdx.x * 256 + threadIdx.x;          // < 16*2304
    int b = i / HW_, k = i - b * HW_;
    float s = 0.f;
#pragma unroll
    for (int lt = 0; lt < 18; lt++)
        s += g_part[((size_t)b * 18 + lt) * HW_ + k];
    g_inv[i] = rsqrtf(s + EPSF);
}

// ---------------------------------------------------------------------------
// 4) Scale rows by per-(b,k) inverse norm. float4 vectorized.
// ---------------------------------------------------------------------------
__global__ __launch_bounds__(256) void normalize_kernel(float* __restrict__ out) {
    const size_t per_b = (size_t)HW_ * HW_ / 4;
    size_t i4 = (size_t)blockIdx.x * blockDim.x + threadIdx.x;
    int b = (int)(i4 / per_b);
    size_t rem = i4 - (size_t)b * per_b;
    int k4 = (int)(rem % (HW_ / 4));
    float4 inv = ((const float4*)g_inv)[b * (HW_ / 4) + k4];
    float4* p = (float4*)out + i4;
    float4 v = *p;
    v.x *= inv.x; v.y *= inv.y; v.z *= inv.z; v.w *= inv.w;
    *p = v;
}

// ---------------------------------------------------------------------------
extern "C" void kernel_launch(void* const* d_in, const int* in_sizes, int n_in,
                              void* d_out, int out_size) {
    const float* A  = (const float*)d_in[0];
    const float* Bf = (const float*)d_in[1];
    float* out = (float*)d_out;

    cudaFuncSetAttribute(corr_gemm, cudaFuncAttributeMaxDynamicSharedMemorySize, SMEM_TOT);

    dim3 pg(C_ / 4, B_, 2);
    prep_kernel<<<pg, 256>>>(A, Bf);

    dim3 gg(18, 18, B_);
    corr_gemm<<<gg, 256, SMEM_TOT>>>(out);

    reduce2_kernel<<<(B_ * HW_) / 256, 256>>>();

    unsigned n4blocks = (unsigned)(((size_t)B_ * HW_ * HW_ / 4) / 256);
    normalize_kernel<<<n4blocks, 256>>>(out);
}

// round 17
// speedup vs baseline: 1.0642x; 1.0438x over previous
#include <cuda_runtime.h>
#include <cuda_fp16.h>
#include <cstdint>

#define B_   16
#define C_   512
#define HW_  2304              // 48*48
#define EPSF 1e-6f
#define HB   8                 // half-batch slice

#define PBSZ   4718592         // per-batch tile bytes (A 2.25MB + B 2.25MB)
#define A_SEC  2359296         // A section size within a batch (18*32*4096)

// ---- scratch: 72 + 2.65 MB = 74.8 MB (< proven-passing 78.3 MB BSS) ----
__device__ char  g_tiles[(size_t)B_ * PBSZ];         // fp16 tiles, all 16 batches
__device__ float g_part[(size_t)B_ * 18 * HW_];      // per-(b,lt) partial ssq per k
__device__ float g_inv[(size_t)B_ * HW_];            // rsqrt per (b,k)

// ---------------- PTX helpers (compute_100-baseline only) ------------------
__device__ __forceinline__ uint32_t smem_u32(const void* p) {
    uint32_t a;
    asm("{ .reg .u64 t; cvta.to.shared.u64 t, %1; cvt.u32.u64 %0, t; }" : "=r"(a) : "l"(p));
    return a;
}
__device__ __forceinline__ void cp16(uint32_t s, const void* g) {
    asm volatile("cp.async.cg.shared.global [%0], [%1], 16;" :: "r"(s), "l"(g) : "memory");
}
__device__ __forceinline__ void cp_commit() {
    asm volatile("cp.async.commit_group;" ::: "memory");
}
template <int N> __device__ __forceinline__ void cp_wait() {
    asm volatile("cp.async.wait_group %0;" :: "n"(N) : "memory");
}
__device__ __forceinline__ void ldsm4t(uint32_t* r, uint32_t a) {
    asm volatile("ldmatrix.sync.aligned.m8n8.x4.trans.shared.b16 {%0,%1,%2,%3}, [%4];"
                 : "=r"(r[0]), "=r"(r[1]), "=r"(r[2]), "=r"(r[3]) : "r"(a));
}
__device__ __forceinline__ void mma16816(float* d, const uint32_t* a, const uint32_t* b) {
    asm volatile(
        "mma.sync.aligned.m16n8k16.row.col.f32.f16.f16.f32 "
        "{%0,%1,%2,%3}, {%4,%5,%6,%7}, {%8,%9}, {%0,%1,%2,%3};"
        : "+f"(d[0]), "+f"(d[1]), "+f"(d[2]), "+f"(d[3])
        : "r"(a[0]), "r"(a[1]), "r"(a[2]), "r"(a[3]), "r"(b[0]), "r"(b[1]));
}
// pack two fp32 -> f16x2 (e0 in low half)
__device__ __forceinline__ uint32_t packh(float e0, float e1) {
    uint32_t u;
    asm("cvt.rn.f16x2.f32 %0, %1, %2;" : "=r"(u) : "f"(e1), "f"(e0));
    return u;
}
// fp16 tile: 16 rows(c) x 128 cols, 256B/row; 16B chunk XOR-swizzled (proven)
#define BSWZ(row, colchunk) ((row) * 256 + ((((colchunk)) ^ ((row) & 7)) << 4))

// ---------------------------------------------------------------------------
// 1) Prep (merged A+B): build ldsm-ready fp16 tile images.
//    blockIdx.z = 0 -> A (permuted l), 1 -> B (identity l).
// ---------------------------------------------------------------------------
__global__ __launch_bounds__(256) void prep_kernel(const float* __restrict__ Asrc,
                                                   const float* __restrict__ Bsrc) {
    __shared__ float sm[4][2352];           // 2304 + pad(l/48): conflict-free
    const int tid = threadIdx.x;
    const int c0 = blockIdx.x * 4, b = blockIdx.y;
    const int isB = blockIdx.z;
    const float* src = isB ? Bsrc : Asrc;
    char* base = g_tiles + (size_t)b * PBSZ + (isB ? A_SEC : 0);

#pragma unroll
    for (int cc = 0; cc < 4; cc++) {
        const float* s = src + (size_t)(b * C_ + c0 + cc) * HW_;
        for (int i = tid; i < HW_; i += 256) {
            int l = isB ? i : ((i % 48) * 48 + i / 48);
            sm[cc][l + l / 48] = s[i];
        }
    }
    __syncthreads();

    for (int idx = tid; idx < 1152; idx += 256) {   // 18 lt * 4 cc * 16 chunks
        int lt = idx / 64, r = idx & 63;
        int cc = r >> 4, chk = r & 15;
        int c = c0 + cc, row = c & 15, ch = c >> 4;
        char* tb = base + (size_t)(lt * 32 + ch) * 4096;
        int l0 = lt * 128 + chk * 8;
        float f[8];
#pragma unroll
        for (int e = 0; e < 8; e++) { int l = l0 + e; f[e] = sm[cc][l + l / 48]; }
        uint32_t h[4];
#pragma unroll
        for (int q = 0; q < 4; q++) h[q] = packh(f[2 * q], f[2 * q + 1]);
        *(uint4*)(tb + BSWZ(row, chk)) = make_uint4(h[0], h[1], h[2], h[3]);
    }
}

// ---------------------------------------------------------------------------
// 2) Pure fp16 mma.sync GEMM — EXACT R12 pipeline (best measured).
//    CTA 128x128, BK=16 chunks of 8KB, 4 stages, 1 chunk per wait+sync.
//    256 threads, 8 warps (2x4), warp tile 64x32. b0-sliced over batches.
// ---------------------------------------------------------------------------
#define NCH 32             // chunks of K=16
#define STG 8192           // stage: A 4K | B 4K
#define SMEM_TOT (4 * STG) // 32KB

__global__ __launch_bounds__(256, 2) void corr_gemm(float* __restrict__ out, int b0) {
    extern __shared__ char smem[];
    const uint32_t sb = smem_u32(smem);
    const int tid = threadIdx.x;
    const int wid = tid >> 5, ln = tid & 31;
    const int wm = wid >> 2, wn = wid & 3;       // 2 x 4 warps

    const int kt = blockIdx.x, lt = blockIdx.y;
    const int b = b0 + blockIdx.z;
    const int k0 = kt * 128, l0 = lt * 128;

    const char* tA = g_tiles + (size_t)b * PBSZ + (size_t)(lt * 32) * 4096;
    const char* tB = g_tiles + (size_t)b * PBSZ + A_SEC + (size_t)(kt * 32) * 4096;

    float acc[4][4][4];
#pragma unroll
    for (int i = 0; i < 4; i++)
#pragma unroll
        for (int j = 0; j < 4; j++)
#pragma unroll
            for (int q = 0; q < 4; q++) acc[i][j][q] = 0.f;

#define LOAD_STAGE(CH) do {                                                    \
        uint32_t st_ = sb + ((CH) & 3) * STG + tid * 16;                       \
        cp16(st_,        tA + (size_t)(CH) * 4096 + tid * 16);                 \
        cp16(st_ + 4096, tB + (size_t)(CH) * 4096 + tid * 16);                 \
    } while (0)

    LOAD_STAGE(0); cp_commit();
    LOAD_STAGE(1); cp_commit();
    LOAD_STAGE(2); cp_commit();

    // ldmatrix.trans addresses (proven formulas)
    const int g8 = ln >> 3, l7 = ln & 7;
    const int akrow = (g8 >> 1) * 8 + l7;
    uint32_t aoff[4], boff[2];
#pragma unroll
    for (int mt = 0; mt < 4; mt++)
        aoff[mt] = BSWZ(akrow, (wm * 64 + mt * 16 + (g8 & 1) * 8) >> 3);
    const int bkrow = (g8 & 1) * 8 + l7;
#pragma unroll
    for (int p = 0; p < 2; p++)
        boff[p] = BSWZ(bkrow, (wn * 32 + p * 16 + (g8 >> 1) * 8) >> 3);

    for (int ch = 0; ch < NCH; ch++) {
        cp_wait<2>();
        __syncthreads();
        if (ch + 3 < NCH) LOAD_STAGE(ch + 3);
        cp_commit();

        const uint32_t st = sb + (ch & 3) * STG;
        uint32_t bb0[4], bb1[4];
        ldsm4t(bb0, st + 4096 + boff[0]);
        ldsm4t(bb1, st + 4096 + boff[1]);
#pragma unroll
        for (int mt = 0; mt < 4; mt++) {
            uint32_t aa[4];
            ldsm4t(aa, st + aoff[mt]);
            mma16816(acc[mt][0], aa, bb0);
            mma16816(acc[mt][1], aa, bb0 + 2);
            mma16816(acc[mt][2], aa, bb1);
            mma16816(acc[mt][3], aa, bb1 + 2);
        }
    }
    cp_wait<0>();

    // Epilogue: ReLU + store + per-thread ssq over its 8 columns
    float ssq[8];
#pragma unroll
    for (int q = 0; q < 8; q++) ssq[q] = 0.f;

    const size_t obase = (size_t)b * HW_ * HW_;
#pragma unroll
    for (int mt = 0; mt < 4; mt++) {
        int l_lo = l0 + wm * 64 + mt * 16 + (ln >> 2);
#pragma unroll
        for (int nt = 0; nt < 4; nt++) {
            int kcol = k0 + wn * 32 + nt * 8 + (ln & 3) * 2;
            float2 v0, v1;
            v0.x = fmaxf(acc[mt][nt][0], 0.f);
            v0.y = fmaxf(acc[mt][nt][1], 0.f);
            v1.x = fmaxf(acc[mt][nt][2], 0.f);
            v1.y = fmaxf(acc[mt][nt][3], 0.f);
            ssq[nt * 2]     += v0.x * v0.x + v1.x * v1.x;
            ssq[nt * 2 + 1] += v0.y * v0.y + v1.y * v1.y;
            *(float2*)(out + obase + (size_t)l_lo * HW_ + kcol)       = v0;
            *(float2*)(out + obase + (size_t)(l_lo + 8) * HW_ + kcol) = v1;
        }
    }

    // Deterministic CTA reduction: red[col 0..127][slot 0..15]
    __syncthreads();
    float* red = (float*)smem;
    const int rslot = wm * 8 + (ln >> 2);
#pragma unroll
    for (int nt = 0; nt < 4; nt++)
#pragma unroll
        for (int e = 0; e < 2; e++) {
            int col = wn * 32 + nt * 8 + (ln & 3) * 2 + e;
            red[col * 17 + rslot] = ssq[nt * 2 + e];
        }
    __syncthreads();
    if (tid < 128) {
        float s = 0.f;
#pragma unroll
        for (int r = 0; r < 16; r++) s += red[tid * 17 + r];
        g_part[((size_t)b * 18 + lt) * HW_ + k0 + tid] = s;
    }
}

// ---------------------------------------------------------------------------
// 3) Reduce 18 partials per (b,k) -> rsqrt. b0-sliced. Deterministic.
// ---------------------------------------------------------------------------
__global__ __launch_bounds__(256) void reduce2_kernel(int b0) {
    int i = blockIdx.x * 256 + threadIdx.x;          // < HB*HW_
    int b = b0 + i / HW_, k = i % HW_;
    float s = 0.f;
#pragma unroll
    for (int lt = 0; lt < 18; lt++)
        s += g_part[((size_t)b * 18 + lt) * HW_ + k];
    g_inv[(size_t)b * HW_ + k] = rsqrtf(s + EPSF);
}

// ---------------------------------------------------------------------------
// 4) Scale rows by per-(b,k) inverse norm. b0-sliced, float4 vectorized.
// ---------------------------------------------------------------------------
__global__ __launch_bounds__(256) void normalize_kernel(float* __restrict__ out, int b0) {
    const size_t per_b = (size_t)HW_ * HW_ / 4;
    size_t i4 = (size_t)blockIdx.x * blockDim.x + threadIdx.x;   // within slice
    int bl = (int)(i4 / per_b);
    size_t rem = i4 - (size_t)bl * per_b;
    int k4 = (int)(rem % (HW_ / 4));
    float4 inv = ((const float4*)g_inv)[(b0 + bl) * (HW_ / 4) + k4];
    float4* p = (float4*)out + (size_t)b0 * per_b + i4;
    float4 v = *p;
    v.x *= inv.x; v.y *= inv.y; v.z *= inv.z; v.w *= inv.w;
    *p = v;
}

// ---------------------------------------------------------------------------
extern "C" void kernel_launch(void* const* d_in, const int* in_sizes, int n_in,
                              void* d_out, int out_size) {
    const float* A  = (const float*)d_in[0];
    const float* Bf = (const float*)d_in[1];
    float* out = (float*)d_out;

    // One-time host resources (no device memory). Work is identical per call.
    static cudaStream_t s2 = nullptr;
    static cudaEvent_t evG0 = nullptr, evJ = nullptr;
    if (s2 == nullptr) {
        cudaStreamCreateWithFlags(&s2, cudaStreamNonBlocking);
        cudaEventCreateWithFlags(&evG0, cudaEventDisableTiming);
        cudaEventCreateWithFlags(&evJ,  cudaEventDisableTiming);
    }

    cudaFuncSetAttribute(corr_gemm, cudaFuncAttributeMaxDynamicSharedMemorySize, SMEM_TOT);

    const unsigned rblocks = (HB * HW_) / 256;                                 // 72
    const unsigned nblocks = (unsigned)(((size_t)HB * HW_ * HW_ / 4) / 256);   // 41472
    dim3 gg(18, 18, HB);

    // main (capture) stream: prep -> gemm(0..7) -> gemm(8..15) -> reduce/norm(8..15)
    dim3 pg(C_ / 4, B_, 2);
    prep_kernel<<<pg, 256>>>(A, Bf);

    corr_gemm<<<gg, 256, SMEM_TOT>>>(out, 0);
    cudaEventRecord(evG0, 0);                       // fork point after first half

    corr_gemm<<<gg, 256, SMEM_TOT>>>(out, HB);

    // side stream: reduce+normalize of first half, overlapped with gemm(8..15)
    cudaStreamWaitEvent(s2, evG0, 0);
    reduce2_kernel<<<rblocks, 256, 0, s2>>>(0);
    normalize_kernel<<<nblocks, 256, 0, s2>>>(out, 0);
    cudaEventRecord(evJ, s2);

    // main stream: second half tail, then join side branch
    reduce2_kernel<<<rblocks, 256>>>(HB);
    normalize_kernel<<<nblocks, 256>>>(out, HB);
    cudaStreamWaitEvent(0, evJ, 0);
}